// round 14
// baseline (speedup 1.0000x reference)
#include <cuda_runtime.h>
#include <cuda_fp16.h>
#include <cstdint>
#include <cstddef>

// ============================================================================
// GCN 2-layer. Simple fork/join (R10-proven): CSR on side stream under GEMM1.
// fp16 mma.sync GEMMs with PRE-TRANSPOSED fp16 weights (coalesced staging),
// src-only CSR payload (weights recomputed from L2-resident dinv at agg time),
// fp16 gather features, fused agg2+log_softmax.
//   h1 = x@W1 (fp16) ; a1 = csr_agg(h1) fp32 ; h2 = relu(a1+b1)@W2 (fp16) ;
//   out = log_softmax(csr_agg(h2) + b2)
//   agg(h)[d] = dinv[d] * ( dinv[d]*h[d] + sum_e dinv[src_e]*h[src_e] )
// ============================================================================

#define NN    100000
#define D1    128
#define D2    64
#define EMAX  1664000
#define SCAN_B 1024
#define NBLK  ((NN + SCAN_B - 1) / SCAN_B)   // 98

typedef unsigned long long u64;

__device__ float  g_dinv[NN];
__device__ int    g_cnt[NN];
__device__ int    g_off[NN];
__device__ int    g_cur[NN];
__device__ int    g_bsum[128];
__device__ int    g_edges[EMAX];             // src only (4B payload)
__device__ __half g_wt1[128 * 128];          // W1^T fp16 [n][k]
__device__ __half g_wt2[64 * 128];           // W2^T fp16 [n][k]
__device__ __half g_h1[(size_t)NN * D1];
__device__ float  g_a1[(size_t)NN * D1];
__device__ __half g_h2[(size_t)NN * D2];
__device__ int    g_is64;

// ---------------------------------------------------------------------------
// PTX helpers
// ---------------------------------------------------------------------------
__device__ __forceinline__ uint32_t smem_to_u32(const void* p) {
    uint32_t a;
    asm("{ .reg .u64 t; cvta.to.shared.u64 t, %1; cvt.u32.u64 %0, t; }"
        : "=r"(a) : "l"(p));
    return a;
}
__device__ __forceinline__ void ldsm_x4(uint32_t* r, uint32_t addr) {
    asm volatile("ldmatrix.sync.aligned.m8n8.x4.shared.b16 {%0,%1,%2,%3}, [%4];"
                 : "=r"(r[0]), "=r"(r[1]), "=r"(r[2]), "=r"(r[3]) : "r"(addr));
}
__device__ __forceinline__ void mma16816(float* c, const uint32_t* a,
                                         const uint32_t* b) {
    asm volatile(
        "mma.sync.aligned.m16n8k16.row.col.f32.f16.f16.f32 "
        "{%0,%1,%2,%3}, {%4,%5,%6,%7}, {%8,%9}, {%0,%1,%2,%3};"
        : "+f"(c[0]), "+f"(c[1]), "+f"(c[2]), "+f"(c[3])
        : "r"(a[0]), "r"(a[1]), "r"(a[2]), "r"(a[3]), "r"(b[0]), "r"(b[1]));
}

// ---------------------------------------------------------------------------
// Edge dtype detection (int64 high words of nonneg < 2^31 are all zero)
// ---------------------------------------------------------------------------
__global__ void detect_kernel(const int* __restrict__ e32) {
    int t = threadIdx.x;
    int nz = (e32[2 * t + 1] != 0) ? 1 : 0;
    int any = __syncthreads_or(nz);
    if (t == 0) g_is64 = (any == 0) ? 1 : 0;
}

__device__ __forceinline__ void load_edge(const void* __restrict__ ei, int e,
                                          int E, int& s, int& d) {
    if (g_is64) {
        const long long* p = (const long long*)ei;
        s = (int)p[e];
        d = (int)p[E + e];
    } else {
        const int* p = (const int*)ei;
        s = p[e];
        d = p[E + e];
    }
}
__device__ __forceinline__ int load_dst(const void* __restrict__ ei, int e,
                                        int E) {
    if (g_is64) return (int)((const long long*)ei)[E + e];
    return ((const int*)ei)[E + e];
}

// ---------------------------------------------------------------------------
// CSR construction (multi-block coalesced scan — proven)
// ---------------------------------------------------------------------------
__global__ void hist_kernel(const void* __restrict__ ei, int E) {
    int e = blockIdx.x * blockDim.x + threadIdx.x;
    if (e >= E) return;
    atomicAdd(&g_cnt[load_dst(ei, e, E)], 1);
}
__global__ void dinv_kernel() {
    int i = blockIdx.x * blockDim.x + threadIdx.x;
    if (i < NN) g_dinv[i] = rsqrtf((float)(1 + g_cnt[i]));
}
__global__ void scan1_kernel() {
    __shared__ int sh[SCAN_B];
    int t = threadIdx.x;
    int i = blockIdx.x * SCAN_B + t;
    int v = (i < NN) ? g_cnt[i] : 0;
    sh[t] = v;
    __syncthreads();
#pragma unroll
    for (int o = 1; o < SCAN_B; o <<= 1) {
        int x = (t >= o) ? sh[t - o] : 0;
        __syncthreads();
        sh[t] += x;
        __syncthreads();
    }
    if (i < NN) g_off[i] = sh[t] - v;
    if (t == SCAN_B - 1) g_bsum[blockIdx.x] = sh[t];
}
__global__ void scan2_kernel(int nb) {
    __shared__ int sh[128];
    int t = threadIdx.x;
    int v = (t < nb) ? g_bsum[t] : 0;
    sh[t] = v;
    __syncthreads();
#pragma unroll
    for (int o = 1; o < 128; o <<= 1) {
        int x = (t >= o) ? sh[t - o] : 0;
        __syncthreads();
        sh[t] += x;
        __syncthreads();
    }
    if (t < nb) g_bsum[t] = sh[t] - v;
}
__global__ void scan3_kernel() {
    int i = blockIdx.x * blockDim.x + threadIdx.x;
    if (i >= NN) return;
    int o = g_off[i] + g_bsum[i >> 10];
    g_off[i] = o;
    g_cur[i] = o;
}
// fill: src-only payload; no dinv dependency, halved traffic vs int2 version
__global__ void fill_kernel(const void* __restrict__ ei, int E) {
    int e = blockIdx.x * blockDim.x + threadIdx.x;
    if (e >= E) return;
    int s, d;
    load_edge(ei, e, E, s, d);
    int pos = atomicAdd(&g_cur[d], 1);
    g_edges[pos] = s;
}

// ---------------------------------------------------------------------------
// Weight pre-transpose: W[k][n] fp32 -> Wt[n][k] fp16 (once, tiny)
// ---------------------------------------------------------------------------
__global__ void transpose_w_kernel(const float* __restrict__ W1,
                                   const float* __restrict__ W2) {
    int i = blockIdx.x * blockDim.x + threadIdx.x;
    if (i < 128 * 128) {
        int k = i >> 7, n = i & 127;             // read coalesced over n
        g_wt1[n * 128 + k] = __float2half(W1[i]);
    }
    if (i < 128 * 64) {
        int k = i / 64, n = i % 64;
        g_wt2[n * 128 + k] = __float2half(W2[i]);
    }
}

// ---------------------------------------------------------------------------
// fp16 mma.sync GEMM, pre-transposed weights: C[M,N](fp16) = A[M,128] @ W
// Per CTA: 128 x N tile, K=128. 512 threads = 16 warps (4x4), warp tile
// 32 x N/4. SMEM: A fp16 [128][136], Wt fp16 [N][136] (272B padded rows).
// B staging now COALESCED (Wt is [n][k] fp16). A := relu(A+bias) optional.
// ---------------------------------------------------------------------------
template <int N, bool FUSE>
__global__ __launch_bounds__(512)
void hgemm_kernel(const float* __restrict__ A, const __half* __restrict__ Bt,
                  const float* __restrict__ bias, __half* __restrict__ C,
                  int M) {
    constexpr int SPB = 272;
    constexpr int OA = 0;
    constexpr int OB = 128 * SPB;
    constexpr int MT = 2;
    constexpr int NT = N / 32;
    static_assert(NT >= 2 && NT % 2 == 0, "NT pairs");

    extern __shared__ char smem[];
    const uint32_t sb = smem_to_u32(smem);
    const int tid = threadIdx.x;
    const int lane = tid & 31;
    const int wid = tid >> 5;
    const int m0 = blockIdx.x * 128;

    // --- A staging: fp32 -> fp16, row-major [m][k], coalesced float4 ---
    for (int i = tid; i < 128 * 32; i += 512) {
        int row = i >> 5;
        int c4 = (i & 31) << 2;
        int gm = m0 + row;
        float4 v = make_float4(0.f, 0.f, 0.f, 0.f);
        if (gm < M) {
            v = *(const float4*)(A + (size_t)gm * 128 + c4);
            if constexpr (FUSE) {
                float4 bb = *(const float4*)(bias + c4);
                v.x = fmaxf(v.x + bb.x, 0.f);
                v.y = fmaxf(v.y + bb.y, 0.f);
                v.z = fmaxf(v.z + bb.z, 0.f);
                v.w = fmaxf(v.w + bb.w, 0.f);
            }
        }
        __half2 p0 = __floats2half2_rn(v.x, v.y);
        __half2 p1 = __floats2half2_rn(v.z, v.w);
        uint2 u = make_uint2(*(uint32_t*)&p0, *(uint32_t*)&p1);
        *(uint2*)(smem + OA + row * SPB + c4 * 2) = u;
    }

    // --- B staging: Wt[n][k] fp16, coalesced uint2 (4 fp16) loads ---
    for (int i = tid; i < N * 32; i += 512) {
        int n = i >> 5;
        int kq = i & 31;
        uint2 u = *(const uint2*)(Bt + (size_t)n * 128 + kq * 4);
        *(uint2*)(smem + OB + n * SPB + kq * 8) = u;
    }
    __syncthreads();

    // --- compute ---
    const int wm = (wid & 3) * 32;
    const int wn = (wid >> 2) * (N / 4);
    const uint32_t aLane = (uint32_t)(lane & 15) * SPB + ((lane >> 4) << 4);
    const uint32_t bLane = (uint32_t)((lane & 7) + ((lane >> 4) << 3)) * SPB
                         + (((lane >> 3) & 1) << 4);
    const uint32_t aB = sb + OA + (uint32_t)wm * SPB + aLane;
    const uint32_t bB = sb + OB + (uint32_t)wn * SPB + bLane;

    float c[MT][NT][4];
#pragma unroll
    for (int i = 0; i < MT; i++)
#pragma unroll
        for (int j = 0; j < NT; j++)
#pragma unroll
            for (int q = 0; q < 4; q++) c[i][j][q] = 0.f;

#pragma unroll
    for (int ks = 0; ks < 8; ks++) {
        uint32_t af[MT][4];
#pragma unroll
        for (int i = 0; i < MT; i++)
            ldsm_x4(af[i], aB + (uint32_t)i * 16 * SPB + ks * 32);
        uint32_t bf[NT / 2][4];
#pragma unroll
        for (int j = 0; j < NT / 2; j++)
            ldsm_x4(bf[j], bB + (uint32_t)j * 16 * SPB + ks * 32);
#pragma unroll
        for (int i = 0; i < MT; i++)
#pragma unroll
            for (int j = 0; j < NT; j++)
                mma16816(c[i][j], af[i], &bf[j >> 1][(j & 1) * 2]);
    }

    // --- epilogue: fp16 out (half2 stores) ---
    const int r0 = m0 + wm + (lane >> 2);
    const int cl = (lane & 3) * 2;
#pragma unroll
    for (int i = 0; i < MT; i++) {
        int row = r0 + i * 16;
#pragma unroll
        for (int j = 0; j < NT; j++) {
            int col = wn + j * 8 + cl;
            if (row < M) {
                __half2 h = __floats2half2_rn(c[i][j][0], c[i][j][1]);
                *(__half2*)(C + (size_t)row * N + col) = h;
            }
            if (row + 8 < M) {
                __half2 h = __floats2half2_rn(c[i][j][2], c[i][j][3]);
                *(__half2*)(C + (size_t)(row + 8) * N + col) = h;
            }
        }
    }
}

// ---------------------------------------------------------------------------
// CSR aggregation, layer 1: warp per dst node, lane owns 4 dims.
// Payload = src only; per-edge weight dinv[src] gathered (L2-resident).
// result = dinv[d] * ( dinv[d]*h[d] + sum_e dinv[s]*h[s] )
// ---------------------------------------------------------------------------
__device__ __forceinline__ float4 h4_to_f4(uint2 u) {
    float2 f0 = __half22float2(*(__half2*)&u.x);
    float2 f1 = __half22float2(*(__half2*)&u.y);
    return make_float4(f0.x, f0.y, f1.x, f1.y);
}

__global__ void agg1_kernel(const __half* __restrict__ h, float* __restrict__ a) {
    int node = (blockIdx.x * blockDim.x + threadIdx.x) >> 5;
    int lane = threadIdx.x & 31;
    if (node >= NN) return;
    int beg = g_off[node];
    int cnt = g_cnt[node];
    float di = g_dinv[node];

    float4 sv = h4_to_f4(((const uint2*)(h + (size_t)node * D1))[lane]);
    float4 acc = make_float4(sv.x * di, sv.y * di, sv.z * di, sv.w * di);
    float4 acc2 = make_float4(0.f, 0.f, 0.f, 0.f);

    for (int base = 0; base < cnt; base += 32) {
        int rem = cnt - base;
        int m = rem < 32 ? rem : 32;
        int es = 0;
        float ew = 0.f;
        if (lane < m) {
            es = g_edges[beg + base + lane];
            ew = g_dinv[es];
        }
        int j = 0;
        for (; j + 1 < m; j += 2) {
            int   s0  = __shfl_sync(0xffffffffu, es, j);
            float w_0 = __shfl_sync(0xffffffffu, ew, j);
            int   s1  = __shfl_sync(0xffffffffu, es, j + 1);
            float w_1 = __shfl_sync(0xffffffffu, ew, j + 1);
            float4 v0 = h4_to_f4(((const uint2*)(h + (size_t)s0 * D1))[lane]);
            float4 v1 = h4_to_f4(((const uint2*)(h + (size_t)s1 * D1))[lane]);
            acc.x  = fmaf(v0.x, w_0, acc.x);
            acc.y  = fmaf(v0.y, w_0, acc.y);
            acc.z  = fmaf(v0.z, w_0, acc.z);
            acc.w  = fmaf(v0.w, w_0, acc.w);
            acc2.x = fmaf(v1.x, w_1, acc2.x);
            acc2.y = fmaf(v1.y, w_1, acc2.y);
            acc2.z = fmaf(v1.z, w_1, acc2.z);
            acc2.w = fmaf(v1.w, w_1, acc2.w);
        }
        if (j < m) {
            int   s0  = __shfl_sync(0xffffffffu, es, j);
            float w_0 = __shfl_sync(0xffffffffu, ew, j);
            float4 v0 = h4_to_f4(((const uint2*)(h + (size_t)s0 * D1))[lane]);
            acc.x = fmaf(v0.x, w_0, acc.x);
            acc.y = fmaf(v0.y, w_0, acc.y);
            acc.z = fmaf(v0.z, w_0, acc.z);
            acc.w = fmaf(v0.w, w_0, acc.w);
        }
    }
    acc.x = di * (acc.x + acc2.x);
    acc.y = di * (acc.y + acc2.y);
    acc.z = di * (acc.z + acc2.z);
    acc.w = di * (acc.w + acc2.w);
    ((float4*)(a + (size_t)node * D1))[lane] = acc;
}

// ---------------------------------------------------------------------------
// CSR aggregation layer 2 (fp16 gather) FUSED with bias + log_softmax.
// ---------------------------------------------------------------------------
__global__ void agg2_softmax_kernel(const __half* __restrict__ h,
                                    const float* __restrict__ b2,
                                    float* __restrict__ out) {
    int node = (blockIdx.x * blockDim.x + threadIdx.x) >> 5;
    int lane = threadIdx.x & 31;
    if (node >= NN) return;
    int beg = g_off[node];
    int cnt = g_cnt[node];
    float di = g_dinv[node];

    float2 sv = __half22float2(((const __half2*)(h + (size_t)node * D2))[lane]);
    float2 acc = make_float2(sv.x * di, sv.y * di);
    float2 acc2 = make_float2(0.f, 0.f);

    for (int base = 0; base < cnt; base += 32) {
        int rem = cnt - base;
        int m = rem < 32 ? rem : 32;
        int es = 0;
        float ew = 0.f;
        if (lane < m) {
            es = g_edges[beg + base + lane];
            ew = g_dinv[es];
        }
        int j = 0;
        for (; j + 1 < m; j += 2) {
            int   s0  = __shfl_sync(0xffffffffu, es, j);
            float w_0 = __shfl_sync(0xffffffffu, ew, j);
            int   s1  = __shfl_sync(0xffffffffu, es, j + 1);
            float w_1 = __shfl_sync(0xffffffffu, ew, j + 1);
            float2 v0 = __half22float2(((const __half2*)(h + (size_t)s0 * D2))[lane]);
            float2 v1 = __half22float2(((const __half2*)(h + (size_t)s1 * D2))[lane]);
            acc.x  = fmaf(v0.x, w_0, acc.x);
            acc.y  = fmaf(v0.y, w_0, acc.y);
            acc2.x = fmaf(v1.x, w_1, acc2.x);
            acc2.y = fmaf(v1.y, w_1, acc2.y);
        }
        if (j < m) {
            int   s0  = __shfl_sync(0xffffffffu, es, j);
            float w_0 = __shfl_sync(0xffffffffu, ew, j);
            float2 v0 = __half22float2(((const __half2*)(h + (size_t)s0 * D2))[lane]);
            acc.x = fmaf(v0.x, w_0, acc.x);
            acc.y = fmaf(v0.y, w_0, acc.y);
        }
    }
    float2 bb = ((const float2*)b2)[lane];
    float v0 = di * (acc.x + acc2.x) + bb.x;
    float v1 = di * (acc.y + acc2.y) + bb.y;
    float mx = fmaxf(v0, v1);
#pragma unroll
    for (int o = 16; o; o >>= 1) mx = fmaxf(mx, __shfl_xor_sync(0xffffffffu, mx, o));
    float s = expf(v0 - mx) + expf(v1 - mx);
#pragma unroll
    for (int o = 16; o; o >>= 1) s += __shfl_xor_sync(0xffffffffu, s, o);
    float ls = mx + logf(s);
    ((float2*)(out + (size_t)node * D2))[lane] = make_float2(v0 - ls, v1 - ls);
}

// ===========================================================================
// Launch: simple fork/join (R10-proven topology)
// ===========================================================================
static constexpr int SMEM_G1 = (128 + 128) * 272;   // 69632
static constexpr int SMEM_G2 = (128 + 64) * 272;    // 52224
static constexpr int GTILES  = (NN + 127) / 128;    // 782

extern "C" void kernel_launch(void* const* d_in, const int* in_sizes, int n_in,
                              void* d_out, int out_size) {
    const float* x  = (const float*)d_in[0];
    const void*  ei = d_in[1];
    const float* W1 = (const float*)d_in[2];
    const float* b1 = (const float*)d_in[3];
    const float* W2 = (const float*)d_in[4];
    const float* b2 = (const float*)d_in[5];
    float* out = (float*)d_out;

    const int E = in_sizes[1] / 2;

    __half* h1 = nullptr; float* a1 = nullptr; __half* h2 = nullptr;
    __half* wt1 = nullptr; __half* wt2 = nullptr; int* cntp = nullptr;
    cudaGetSymbolAddress((void**)&h1, g_h1);
    cudaGetSymbolAddress((void**)&a1, g_a1);
    cudaGetSymbolAddress((void**)&h2, g_h2);
    cudaGetSymbolAddress((void**)&wt1, g_wt1);
    cudaGetSymbolAddress((void**)&wt2, g_wt2);
    cudaGetSymbolAddress((void**)&cntp, g_cnt);

    static cudaStream_t side = nullptr;
    static cudaEvent_t evF = nullptr, evJ = nullptr;
    if (side == nullptr) {
        cudaStreamCreateWithFlags(&side, cudaStreamNonBlocking);
        cudaEventCreateWithFlags(&evF, cudaEventDisableTiming);
        cudaEventCreateWithFlags(&evJ, cudaEventDisableTiming);
        cudaFuncSetAttribute(hgemm_kernel<128, false>,
                             cudaFuncAttributeMaxDynamicSharedMemorySize, SMEM_G1);
        cudaFuncSetAttribute(hgemm_kernel<64, true>,
                             cudaFuncAttributeMaxDynamicSharedMemorySize, SMEM_G2);
    }

    // ---- fork: CSR build on side stream while GEMM1 runs on main ----
    cudaEventRecord(evF, 0);
    cudaStreamWaitEvent(side, evF, 0);

    detect_kernel<<<1, 1024, 0, side>>>((const int*)ei);
    cudaMemsetAsync(cntp, 0, NN * sizeof(int), side);
    hist_kernel<<<(E + 255) / 256, 256, 0, side>>>(ei, E);
    dinv_kernel<<<(NN + 255) / 256, 256, 0, side>>>();
    scan1_kernel<<<NBLK, SCAN_B, 0, side>>>();
    scan2_kernel<<<1, 128, 0, side>>>(NBLK);
    scan3_kernel<<<(NN + 255) / 256, 256, 0, side>>>();
    fill_kernel<<<(E + 255) / 256, 256, 0, side>>>(ei, E);
    cudaEventRecord(evJ, side);

    // main: weight transpose (tiny), then h1 = x @ W1 (fp16 mma)
    transpose_w_kernel<<<64, 256>>>(W1, W2);
    hgemm_kernel<128, false><<<GTILES, 512, SMEM_G1>>>(x, wt1, nullptr, h1, NN);

    // ---- join ----
    cudaStreamWaitEvent(0, evJ, 0);

    // a1 = CSR aggregate of h1 (self loop folded)
    agg1_kernel<<<(NN * 32 + 255) / 256, 256>>>(h1, a1);

    // h2 = relu(a1 + b1) @ W2 (fp16 mma, fused bias+relu)
    hgemm_kernel<64, true><<<GTILES, 512, SMEM_G2>>>(a1, wt2, b1, h2, NN);

    // out = log_softmax(CSR aggregate of h2 + b2)
    agg2_softmax_kernel<<<(NN * 32 + 255) / 256, 256>>>(h2, b2, out);
}

// round 17
// speedup vs baseline: 1.0760x; 1.0760x over previous
#include <cuda_runtime.h>
#include <cuda_fp16.h>
#include <cstdint>
#include <cstddef>

// ============================================================================
// GCN 2-layer. R10-proven engine: f32x2 double-buffered SGEMMs (fp16 out),
// CSR on side stream under GEMM1 (src-only payload), fp16 gather features,
// agg1/GEMM2 half-pipelined, fused agg2+log_softmax.
//   h1 = x@W1 (fp16) ; a1 = csr_agg(h1) fp32 ; h2 = relu(a1+b1)@W2 (fp16) ;
//   out = log_softmax(csr_agg(h2) + b2)
//   agg(h)[d] = dinv[d] * ( dinv[d]*h[d] + sum_e dinv[src_e]*h[src_e] )
// ============================================================================

#define NN    100000
#define D1    128
#define D2    64
#define EMAX  1664000
#define SCAN_B 1024
#define NBLK  ((NN + SCAN_B - 1) / SCAN_B)   // 98
#define NH    50048                          // half split (391 * 128)

typedef unsigned long long u64;

__device__ float  g_dinv[NN];
__device__ int    g_cnt[NN];
__device__ int    g_off[NN];
__device__ int    g_cur[NN];
__device__ int    g_bsum[128];
__device__ int    g_edges[EMAX];             // src only (4B payload)
__device__ __half g_h1[(size_t)NN * D1];
__device__ float  g_a1[(size_t)NN * D1];
__device__ __half g_h2[(size_t)NN * D2];
__device__ int    g_is64;

// ---------------------------------------------------------------------------
// f32x2 packed math (sm_100+)
// ---------------------------------------------------------------------------
__device__ __forceinline__ u64 pack2(float lo, float hi) {
    u64 r;
    asm("mov.b64 %0, {%1, %2};" : "=l"(r) : "f"(lo), "f"(hi));
    return r;
}
__device__ __forceinline__ void ffma2(u64& d, u64 a, u64 b) {
    asm("fma.rn.f32x2 %0, %1, %2, %0;" : "+l"(d) : "l"(a), "l"(b));
}
__device__ __forceinline__ float2 unpack2(u64 v) {
    float2 f;
    asm("mov.b64 {%0, %1}, %2;" : "=f"(f.x), "=f"(f.y) : "l"(v));
    return f;
}

// ---------------------------------------------------------------------------
// Edge dtype detection (int64 high words of nonneg < 2^31 are all zero)
// ---------------------------------------------------------------------------
__global__ void detect_kernel(const int* __restrict__ e32) {
    int t = threadIdx.x;
    int nz = (e32[2 * t + 1] != 0) ? 1 : 0;
    int any = __syncthreads_or(nz);
    if (t == 0) g_is64 = (any == 0) ? 1 : 0;
}

__device__ __forceinline__ void load_edge(const void* __restrict__ ei, int e,
                                          int E, int& s, int& d) {
    if (g_is64) {
        const long long* p = (const long long*)ei;
        s = (int)p[e];
        d = (int)p[E + e];
    } else {
        const int* p = (const int*)ei;
        s = p[e];
        d = p[E + e];
    }
}
__device__ __forceinline__ int load_dst(const void* __restrict__ ei, int e,
                                        int E) {
    if (g_is64) return (int)((const long long*)ei)[E + e];
    return ((const int*)ei)[E + e];
}

// ---------------------------------------------------------------------------
// CSR construction (multi-block coalesced scan — proven)
// ---------------------------------------------------------------------------
__global__ void hist_kernel(const void* __restrict__ ei, int E) {
    int e = blockIdx.x * blockDim.x + threadIdx.x;
    if (e >= E) return;
    atomicAdd(&g_cnt[load_dst(ei, e, E)], 1);
}
__global__ void dinv_kernel() {
    int i = blockIdx.x * blockDim.x + threadIdx.x;
    if (i < NN) g_dinv[i] = rsqrtf((float)(1 + g_cnt[i]));
}
__global__ void scan1_kernel() {
    __shared__ int sh[SCAN_B];
    int t = threadIdx.x;
    int i = blockIdx.x * SCAN_B + t;
    int v = (i < NN) ? g_cnt[i] : 0;
    sh[t] = v;
    __syncthreads();
#pragma unroll
    for (int o = 1; o < SCAN_B; o <<= 1) {
        int x = (t >= o) ? sh[t - o] : 0;
        __syncthreads();
        sh[t] += x;
        __syncthreads();
    }
    if (i < NN) g_off[i] = sh[t] - v;
    if (t == SCAN_B - 1) g_bsum[blockIdx.x] = sh[t];
}
__global__ void scan2_kernel(int nb) {
    __shared__ int sh[128];
    int t = threadIdx.x;
    int v = (t < nb) ? g_bsum[t] : 0;
    sh[t] = v;
    __syncthreads();
#pragma unroll
    for (int o = 1; o < 128; o <<= 1) {
        int x = (t >= o) ? sh[t - o] : 0;
        __syncthreads();
        sh[t] += x;
        __syncthreads();
    }
    if (t < nb) g_bsum[t] = sh[t] - v;
}
__global__ void scan3_kernel() {
    int i = blockIdx.x * blockDim.x + threadIdx.x;
    if (i >= NN) return;
    int o = g_off[i] + g_bsum[i >> 10];
    g_off[i] = o;
    g_cur[i] = o;
}
// fill: src-only payload; no dinv dependency, halved write traffic
__global__ void fill_kernel(const void* __restrict__ ei, int E) {
    int e = blockIdx.x * blockDim.x + threadIdx.x;
    if (e >= E) return;
    int s, d;
    load_edge(ei, e, E, s, d);
    int pos = atomicAdd(&g_cur[d], 1);
    g_edges[pos] = s;
}

// ---------------------------------------------------------------------------
// Pipelined, double-buffered SGEMM, f32x2 inner product, fp16 output.
// C[M,N](fp16) = A[M,K] @ B[K,N]; optionally A := relu(A + bias[k]) on load.
// mbase offsets the row range (for split GEMM2 launches).
// ---------------------------------------------------------------------------
template <int BM, int BN, int BK, int TM, int TN, bool FUSE_RELU_BIAS>
__global__ __launch_bounds__(256)
void sgemm_kernel(const float* __restrict__ A, const float* __restrict__ B,
                  const float* __restrict__ bias, __half* __restrict__ C,
                  int M, int N, int K, int mbase) {
    __shared__ float As[2][BK][BM + 4];
    __shared__ float Bs[2][BK][BN];

    constexpr int TX = BN / TN;
    static_assert((BM / TM) * TX == 256, "thread count");
    constexpr int KQ = BK / 4;
    constexpr int AQ = BM * BK / 4;
    constexpr int NQ = BN / 4;
    constexpr int BQ = BK * BN / 4;
    constexpr int TNH = TN / 2;
    constexpr int ALD = AQ / 256;
    constexpr int BLD = BQ / 256;
    static_assert(ALD * 256 == AQ && BLD * 256 == BQ, "exact split");

    const int tid = threadIdx.x;
    const int m0 = mbase + blockIdx.y * BM;
    const int n0 = blockIdx.x * BN;
    const int tx = tid % TX;
    const int ty = tid / TX;

    float4 ar[ALD];
    float4 br[BLD];

    u64 acc[TM][TNH];
#pragma unroll
    for (int i = 0; i < TM; i++)
#pragma unroll
        for (int j = 0; j < TNH; j++) acc[i][j] = 0ull;

    auto load_tiles = [&](int kt) {
#pragma unroll
        for (int u = 0; u < ALD; u++) {
            int i = tid + u * 256;
            int ml = i / KQ;
            int kq = i % KQ;
            int gm = m0 + ml;
            float4 v = make_float4(0.f, 0.f, 0.f, 0.f);
            if (gm < M) {
                v = *(const float4*)(A + (size_t)gm * K + kt + kq * 4);
                if (FUSE_RELU_BIAS) {
                    float4 bb = *(const float4*)(bias + kt + kq * 4);
                    v.x = fmaxf(v.x + bb.x, 0.f);
                    v.y = fmaxf(v.y + bb.y, 0.f);
                    v.z = fmaxf(v.z + bb.z, 0.f);
                    v.w = fmaxf(v.w + bb.w, 0.f);
                }
            }
            ar[u] = v;
        }
#pragma unroll
        for (int u = 0; u < BLD; u++) {
            int i = tid + u * 256;
            int kl = i / NQ;
            int nq = i % NQ;
            br[u] = *(const float4*)(B + (size_t)(kt + kl) * N + n0 + nq * 4);
        }
    };
    auto store_tiles = [&](int b) {
#pragma unroll
        for (int u = 0; u < ALD; u++) {
            int i = tid + u * 256;
            int ml = i / KQ;
            int kq = i % KQ;
            As[b][kq * 4 + 0][ml] = ar[u].x;
            As[b][kq * 4 + 1][ml] = ar[u].y;
            As[b][kq * 4 + 2][ml] = ar[u].z;
            As[b][kq * 4 + 3][ml] = ar[u].w;
        }
#pragma unroll
        for (int u = 0; u < BLD; u++) {
            int i = tid + u * 256;
            int kl = i / NQ;
            int nq = i % NQ;
            *(float4*)(&Bs[b][kl][nq * 4]) = br[u];
        }
    };

    load_tiles(0);
    store_tiles(0);
    __syncthreads();

    int buf = 0;
    for (int kt = 0; kt < K; kt += BK) {
        const int ktn = kt + BK;
        const bool has_next = ktn < K;
        if (has_next) load_tiles(ktn);

#pragma unroll
        for (int k = 0; k < BK; k++) {
            float a[TM];
#pragma unroll
            for (int i = 0; i < TM; i += 4)
                *(float4*)&a[i] = *(const float4*)&As[buf][k][ty * TM + i];
            u64 b2r[TNH];
#pragma unroll
            for (int j = 0; j < TNH; j++)
                b2r[j] = *(const u64*)&Bs[buf][k][tx * TN + 2 * j];
#pragma unroll
            for (int i = 0; i < TM; i++) {
                u64 a2 = pack2(a[i], a[i]);
#pragma unroll
                for (int j = 0; j < TNH; j++)
                    ffma2(acc[i][j], a2, b2r[j]);
            }
        }

        if (has_next) {
            store_tiles(buf ^ 1);
            __syncthreads();
            buf ^= 1;
        }
    }

    // ---- epilogue: fp16 out ----
#pragma unroll
    for (int i = 0; i < TM; i++) {
        int gm = m0 + ty * TM + i;
        if (gm < M) {
            uint32_t hw[TNH];
#pragma unroll
            for (int j = 0; j < TNH; j++) {
                float2 f = unpack2(acc[i][j]);
                __half2 h2v = __floats2half2_rn(f.x, f.y);
                hw[j] = *(uint32_t*)&h2v;
            }
            if constexpr (TNH == 4) {
                uint4 v = make_uint4(hw[0], hw[1], hw[2], hw[3]);
                *(uint4*)(C + (size_t)gm * N + n0 + tx * TN) = v;
            } else {
                uint2 v = make_uint2(hw[0], hw[1]);
                *(uint2*)(C + (size_t)gm * N + n0 + tx * TN) = v;
            }
        }
    }
}

// ---------------------------------------------------------------------------
// CSR aggregation, layer 1 (node range [n0, n1)): warp per dst node,
// lane owns 4 dims. src-only payload; weight = dinv[src] (L2-resident).
// result = dinv[d] * ( dinv[d]*h[d] + sum_e dinv[s]*h[s] )
// ---------------------------------------------------------------------------
__device__ __forceinline__ float4 h4_to_f4(uint2 u) {
    float2 f0 = __half22float2(*(__half2*)&u.x);
    float2 f1 = __half22float2(*(__half2*)&u.y);
    return make_float4(f0.x, f0.y, f1.x, f1.y);
}

__global__ void agg1_kernel(const __half* __restrict__ h, float* __restrict__ a,
                            int n0, int n1) {
    int node = n0 + ((blockIdx.x * blockDim.x + threadIdx.x) >> 5);
    int lane = threadIdx.x & 31;
    if (node >= n1) return;
    int beg = g_off[node];
    int cnt = g_cnt[node];
    float di = g_dinv[node];

    float4 sv = h4_to_f4(((const uint2*)(h + (size_t)node * D1))[lane]);
    float4 acc = make_float4(sv.x * di, sv.y * di, sv.z * di, sv.w * di);
    float4 acc2 = make_float4(0.f, 0.f, 0.f, 0.f);

    for (int base = 0; base < cnt; base += 32) {
        int rem = cnt - base;
        int m = rem < 32 ? rem : 32;
        int es = 0;
        float ew = 0.f;
        if (lane < m) {
            es = g_edges[beg + base + lane];
            ew = g_dinv[es];
        }
        int j = 0;
        for (; j + 1 < m; j += 2) {
            int   s0  = __shfl_sync(0xffffffffu, es, j);
            float w_0 = __shfl_sync(0xffffffffu, ew, j);
            int   s1  = __shfl_sync(0xffffffffu, es, j + 1);
            float w_1 = __shfl_sync(0xffffffffu, ew, j + 1);
            float4 v0 = h4_to_f4(((const uint2*)(h + (size_t)s0 * D1))[lane]);
            float4 v1 = h4_to_f4(((const uint2*)(h + (size_t)s1 * D1))[lane]);
            acc.x  = fmaf(v0.x, w_0, acc.x);
            acc.y  = fmaf(v0.y, w_0, acc.y);
            acc.z  = fmaf(v0.z, w_0, acc.z);
            acc.w  = fmaf(v0.w, w_0, acc.w);
            acc2.x = fmaf(v1.x, w_1, acc2.x);
            acc2.y = fmaf(v1.y, w_1, acc2.y);
            acc2.z = fmaf(v1.z, w_1, acc2.z);
            acc2.w = fmaf(v1.w, w_1, acc2.w);
        }
        if (j < m) {
            int   s0  = __shfl_sync(0xffffffffu, es, j);
            float w_0 = __shfl_sync(0xffffffffu, ew, j);
            float4 v0 = h4_to_f4(((const uint2*)(h + (size_t)s0 * D1))[lane]);
            acc.x = fmaf(v0.x, w_0, acc.x);
            acc.y = fmaf(v0.y, w_0, acc.y);
            acc.z = fmaf(v0.z, w_0, acc.z);
            acc.w = fmaf(v0.w, w_0, acc.w);
        }
    }
    acc.x = di * (acc.x + acc2.x);
    acc.y = di * (acc.y + acc2.y);
    acc.z = di * (acc.z + acc2.z);
    acc.w = di * (acc.w + acc2.w);
    ((float4*)(a + (size_t)node * D1))[lane] = acc;
}

// ---------------------------------------------------------------------------
// CSR aggregation layer 2 (fp16 gather) FUSED with bias + log_softmax.
// ---------------------------------------------------------------------------
__global__ void agg2_softmax_kernel(const __half* __restrict__ h,
                                    const float* __restrict__ b2,
                                    float* __restrict__ out) {
    int node = (blockIdx.x * blockDim.x + threadIdx.x) >> 5;
    int lane = threadIdx.x & 31;
    if (node >= NN) return;
    int beg = g_off[node];
    int cnt = g_cnt[node];
    float di = g_dinv[node];

    float2 sv = __half22float2(((const __half2*)(h + (size_t)node * D2))[lane]);
    float2 acc = make_float2(sv.x * di, sv.y * di);
    float2 acc2 = make_float2(0.f, 0.f);

    for (int base = 0; base < cnt; base += 32) {
        int rem = cnt - base;
        int m = rem < 32 ? rem : 32;
        int es = 0;
        float ew = 0.f;
        if (lane < m) {
            es = g_edges[beg + base + lane];
            ew = g_dinv[es];
        }
        int j = 0;
        for (; j + 1 < m; j += 2) {
            int   s0  = __shfl_sync(0xffffffffu, es, j);
            float w_0 = __shfl_sync(0xffffffffu, ew, j);
            int   s1  = __shfl_sync(0xffffffffu, es, j + 1);
            float w_1 = __shfl_sync(0xffffffffu, ew, j + 1);
            float2 v0 = __half22float2(((const __half2*)(h + (size_t)s0 * D2))[lane]);
            float2 v1 = __half22float2(((const __half2*)(h + (size_t)s1 * D2))[lane]);
            acc.x  = fmaf(v0.x, w_0, acc.x);
            acc.y  = fmaf(v0.y, w_0, acc.y);
            acc2.x = fmaf(v1.x, w_1, acc2.x);
            acc2.y = fmaf(v1.y, w_1, acc2.y);
        }
        if (j < m) {
            int   s0  = __shfl_sync(0xffffffffu, es, j);
            float w_0 = __shfl_sync(0xffffffffu, ew, j);
            float2 v0 = __half22float2(((const __half2*)(h + (size_t)s0 * D2))[lane]);
            acc.x = fmaf(v0.x, w_0, acc.x);
            acc.y = fmaf(v0.y, w_0, acc.y);
        }
    }
    float2 bb = ((const float2*)b2)[lane];
    float v0 = di * (acc.x + acc2.x) + bb.x;
    float v1 = di * (acc.y + acc2.y) + bb.y;
    float mx = fmaxf(v0, v1);
#pragma unroll
    for (int o = 16; o; o >>= 1) mx = fmaxf(mx, __shfl_xor_sync(0xffffffffu, mx, o));
    float s = expf(v0 - mx) + expf(v1 - mx);
#pragma unroll
    for (int o = 16; o; o >>= 1) s += __shfl_xor_sync(0xffffffffu, s, o);
    float ls = mx + logf(s);
    ((float2*)(out + (size_t)node * D2))[lane] = make_float2(v0 - ls, v1 - ls);
}

// ===========================================================================
// Launch
// ===========================================================================
static constexpr int HTILES = NH / 128;             // 391
static constexpr int GTILES = (NN + 127) / 128;     // 782

extern "C" void kernel_launch(void* const* d_in, const int* in_sizes, int n_in,
                              void* d_out, int out_size) {
    const float* x  = (const float*)d_in[0];
    const void*  ei = d_in[1];
    const float* W1 = (const float*)d_in[2];
    const float* b1 = (const float*)d_in[3];
    const float* W2 = (const float*)d_in[4];
    const float* b2 = (const float*)d_in[5];
    float* out = (float*)d_out;

    const int E = in_sizes[1] / 2;

    __half* h1 = nullptr; float* a1 = nullptr; __half* h2 = nullptr;
    int* cntp = nullptr;
    cudaGetSymbolAddress((void**)&h1, g_h1);
    cudaGetSymbolAddress((void**)&a1, g_a1);
    cudaGetSymbolAddress((void**)&h2, g_h2);
    cudaGetSymbolAddress((void**)&cntp, g_cnt);

    static cudaStream_t side = nullptr;
    static cudaEvent_t evF = nullptr, evJ = nullptr;
    static cudaEvent_t evH0 = nullptr, evH1 = nullptr, evG = nullptr;
    if (side == nullptr) {
        cudaStreamCreateWithFlags(&side, cudaStreamNonBlocking);
        cudaEventCreateWithFlags(&evF, cudaEventDisableTiming);
        cudaEventCreateWithFlags(&evJ, cudaEventDisableTiming);
        cudaEventCreateWithFlags(&evH0, cudaEventDisableTiming);
        cudaEventCreateWithFlags(&evH1, cudaEventDisableTiming);
        cudaEventCreateWithFlags(&evG, cudaEventDisableTiming);
    }

    // ---- fork: CSR build on side stream while GEMM1 runs on main ----
    cudaEventRecord(evF, 0);
    cudaStreamWaitEvent(side, evF, 0);

    detect_kernel<<<1, 1024, 0, side>>>((const int*)ei);
    cudaMemsetAsync(cntp, 0, NN * sizeof(int), side);
    hist_kernel<<<(E + 255) / 256, 256, 0, side>>>(ei, E);
    dinv_kernel<<<(NN + 255) / 256, 256, 0, side>>>();
    scan1_kernel<<<NBLK, SCAN_B, 0, side>>>();
    scan2_kernel<<<1, 128, 0, side>>>(NBLK);
    scan3_kernel<<<(NN + 255) / 256, 256, 0, side>>>();
    fill_kernel<<<(E + 255) / 256, 256, 0, side>>>(ei, E);
    cudaEventRecord(evJ, side);

    // main: h1 = x @ W1  (f32x2 SGEMM, fp16 out)
    {
        dim3 grid(D1 / 128, GTILES);
        sgemm_kernel<128, 128, 16, 8, 8, false><<<grid, 256>>>(
            x, W1, nullptr, h1, NN, D1, D1, 0);
    }

    // ---- join CSR ----
    cudaStreamWaitEvent(0, evJ, 0);

    // agg1 half 0 on main; GEMM2 half 0 chases on side under agg1 half 1.
    agg1_kernel<<<(NH * 32 + 255) / 256, 256>>>(h1, a1, 0, NH);
    cudaEventRecord(evH0, 0);

    cudaStreamWaitEvent(side, evH0, 0);
    {
        dim3 grid(D2 / 64, HTILES);
        sgemm_kernel<128, 64, 16, 8, 4, true><<<grid, 256, 0, side>>>(
            a1, W2, b1, h2, NN, D2, D1, 0);
    }

    agg1_kernel<<<((NN - NH) * 32 + 255) / 256, 256>>>(h1, a1, NH, NN);
    cudaEventRecord(evH1, 0);

    cudaStreamWaitEvent(side, evH1, 0);
    {
        dim3 grid(D2 / 64, GTILES - HTILES);
        sgemm_kernel<128, 64, 16, 8, 4, true><<<grid, 256, 0, side>>>(
            a1, W2, b1, h2, NN, D2, D1, NH);
    }
    cudaEventRecord(evG, side);

    // ---- join GEMM2, fused agg2 + log_softmax ----
    cudaStreamWaitEvent(0, evG, 0);
    agg2_softmax_kernel<<<(NN * 32 + 255) / 256, 256>>>(h2, b2, out);
}